// round 1
// baseline (speedup 1.0000x reference)
#include <cuda_runtime.h>
#include <math.h>

// Problem constants
#define TAU   0.07f
#define BB    8
#define CC    128
#define HH    512
#define WW    512
#define HWSZ  (HH*WW)          // 262144
#define KK    64
#define NNEG  7
#define PP    4096
#define NQ    (BB*KK)          // 512
#define QT    4                // queries per block
#define NBLK  (NQ/QT)          // 128

// Transposed normalized pool: [CC/4][PP] of float4.
// Element (chunk i, row p) at g_pool_t[i*PP + p] holds channels 4i..4i+3 of pool row p.
__device__ float4 g_pool_t[(CC/4) * PP];
__device__ float  g_partial[NBLK];

// ---------------------------------------------------------------------------
// Kernel 1: L2-normalize the positive pool and store transposed (float4-major)
// grid = PP blocks, 128 threads (one per channel)
// ---------------------------------------------------------------------------
__global__ void prep_pool_kernel(const float* __restrict__ pool) {
    __shared__ float red[CC];
    int r = blockIdx.x;
    int t = threadIdx.x;
    float v = pool[r * CC + t];
    red[t] = v * v;
    __syncthreads();
    #pragma unroll
    for (int s = 64; s >= 1; s >>= 1) {
        if (t < s) red[t] += red[t + s];
        __syncthreads();
    }
    float inv = 1.0f / fmaxf(sqrtf(red[0]), 1e-12f);
    float nv = v * inv;
    // transposed scatter: chunk i = t/4, component t%4
    ((float*)g_pool_t)[((t >> 2) * PP + r) * 4 + (t & 3)] = nv;
}

// ---------------------------------------------------------------------------
// Kernel 2: main — gather+normalize QT queries, argmax over pool, negatives,
// per-query CE loss; write per-block partial sum (deterministic).
// grid = NBLK blocks, 256 threads
// ---------------------------------------------------------------------------
__global__ void __launch_bounds__(256, 2)
main_kernel(const float* __restrict__ qf,
            const float* __restrict__ negs,
            const int*   __restrict__ qidx) {
    __shared__ float4 qs4[QT * (CC/4)];     // normalized queries, 4 x 128 floats
    __shared__ float  red[QT * CC];         // 512 floats for sumsq reduction
    __shared__ float  smv[QT * 256];
    __shared__ int    smi[QT * 256];
    __shared__ float  loss_sm[QT];

    float* qs = (float*)qs4;
    int t = threadIdx.x;
    int g = blockIdx.x;

    // ---- gather QT*CC = 512 elements (2 per thread), strided from feature map
    for (int e = t; e < QT * CC; e += 256) {
        int ql = e >> 7, c = e & 127;
        int qg = g * QT + ql;
        int b = qg >> 6, k = qg & 63;
        int idx = qidx[b * KK + k];
        qs[e] = qf[(long)(b * CC + c) * HWSZ + idx];
    }
    __syncthreads();
    for (int e = t; e < QT * CC; e += 256) red[e] = qs[e] * qs[e];
    __syncthreads();
    for (int s = 64; s >= 1; s >>= 1) {
        for (int e = t; e < QT * CC; e += 256) {
            int c = e & 127;
            if (c < s) red[e] += red[e + s];
        }
        __syncthreads();
    }
    for (int e = t; e < QT * CC; e += 256) {
        int ql = e >> 7;
        float inv = 1.0f / fmaxf(sqrtf(red[ql * CC]), 1e-12f);
        qs[e] *= inv;
    }
    __syncthreads();

    // ---- argmax over pool: each thread handles rows p = t, t+256, ...
    const float4* q0 = &qs4[0 * (CC/4)];
    const float4* q1 = &qs4[1 * (CC/4)];
    const float4* q2 = &qs4[2 * (CC/4)];
    const float4* q3 = &qs4[3 * (CC/4)];

    float mx0 = -1e30f, mx1 = -1e30f, mx2 = -1e30f, mx3 = -1e30f;
    int   mi0 = 0, mi1 = 0, mi2 = 0, mi3 = 0;

    for (int p = t; p < PP; p += 256) {
        float a0 = 0.f, a1 = 0.f, a2 = 0.f, a3 = 0.f;
        #pragma unroll
        for (int i = 0; i < CC/4; i++) {
            float4 pv = g_pool_t[i * PP + p];   // coalesced: lanes -> consecutive p
            float4 u;
            u = q0[i]; a0 += pv.x*u.x + pv.y*u.y + pv.z*u.z + pv.w*u.w;
            u = q1[i]; a1 += pv.x*u.x + pv.y*u.y + pv.z*u.z + pv.w*u.w;
            u = q2[i]; a2 += pv.x*u.x + pv.y*u.y + pv.z*u.z + pv.w*u.w;
            u = q3[i]; a3 += pv.x*u.x + pv.y*u.y + pv.z*u.z + pv.w*u.w;
        }
        if (a0 > mx0) { mx0 = a0; mi0 = p; }
        if (a1 > mx1) { mx1 = a1; mi1 = p; }
        if (a2 > mx2) { mx2 = a2; mi2 = p; }
        if (a3 > mx3) { mx3 = a3; mi3 = p; }
    }

    smv[0*256 + t] = mx0; smi[0*256 + t] = mi0;
    smv[1*256 + t] = mx1; smi[1*256 + t] = mi1;
    smv[2*256 + t] = mx2; smi[2*256 + t] = mi2;
    smv[3*256 + t] = mx3; smi[3*256 + t] = mi3;
    __syncthreads();

    for (int s = 128; s >= 1; s >>= 1) {
        if (t < s) {
            #pragma unroll
            for (int q = 0; q < QT; q++) {
                float v2 = smv[q*256 + t + s]; int i2 = smi[q*256 + t + s];
                float v1 = smv[q*256 + t];     int i1 = smi[q*256 + t];
                if (v2 > v1 || (v2 == v1 && i2 < i1)) {
                    smv[q*256 + t] = v2; smi[q*256 + t] = i2;
                }
            }
        }
        __syncthreads();
    }

    // ---- negatives + loss: warp w (0..3) handles query ql = w
    int w = t >> 5, lane = t & 31;
    if (w < QT) {
        int ql = w;
        int qg = g * QT + ql;
        int b = qg >> 6, k = qg & 63;

        float l[1 + NNEG];
        l[0] = smv[ql * 256] / TAU;   // max cosine sim == dot(q_norm, pos_proto)

        const float4* qv4 = &qs4[ql * (CC/4)];
        float4 qv = qv4[lane];
        #pragma unroll
        for (int n = 0; n < NNEG; n++) {
            const float4* np = (const float4*)&negs[(((long)(b * KK + k)) * NNEG + n) * CC];
            float4 nv = np[lane];
            float ss = nv.x*nv.x + nv.y*nv.y + nv.z*nv.z + nv.w*nv.w;
            float dt = nv.x*qv.x + nv.y*qv.y + nv.z*qv.z + nv.w*qv.w;
            #pragma unroll
            for (int o = 16; o > 0; o >>= 1) {
                ss += __shfl_xor_sync(0xFFFFFFFFu, ss, o);
                dt += __shfl_xor_sync(0xFFFFFFFFu, dt, o);
            }
            l[n + 1] = (dt / fmaxf(sqrtf(ss), 1e-12f)) / TAU;
        }
        if (lane == 0) {
            float m = l[0];
            #pragma unroll
            for (int i = 1; i <= NNEG; i++) m = fmaxf(m, l[i]);
            float sum = 0.f;
            #pragma unroll
            for (int i = 0; i <= NNEG; i++) sum += expf(l[i] - m);
            loss_sm[ql] = m + logf(sum) - l[0];   // lse - l0
        }
    }
    __syncthreads();
    if (t == 0) {
        g_partial[g] = loss_sm[0] + loss_sm[1] + loss_sm[2] + loss_sm[3];
    }
}

// ---------------------------------------------------------------------------
// Kernel 3: deterministic final sum + mean
// ---------------------------------------------------------------------------
__global__ void finalize_kernel(float* out) {
    __shared__ float red[NBLK];
    int t = threadIdx.x;
    red[t] = g_partial[t];
    __syncthreads();
    #pragma unroll
    for (int s = NBLK/2; s >= 1; s >>= 1) {
        if (t < s) red[t] += red[t + s];
        __syncthreads();
    }
    if (t == 0) out[0] = red[0] / (float)NQ;
}

extern "C" void kernel_launch(void* const* d_in, const int* in_sizes, int n_in,
                              void* d_out, int out_size) {
    const float* query_feat = (const float*)d_in[0];
    const float* pos_pool   = (const float*)d_in[1];
    const float* neg_protos = (const float*)d_in[2];
    const int*   query_idx  = (const int*)d_in[3];
    float* out = (float*)d_out;

    prep_pool_kernel<<<PP, CC>>>(pos_pool);
    main_kernel<<<NBLK, 256>>>(query_feat, neg_protos, query_idx);
    finalize_kernel<<<1, NBLK>>>(out);
}

// round 2
// speedup vs baseline: 4.7752x; 4.7752x over previous
#include <cuda_runtime.h>
#include <math.h>

// Problem constants
#define TAU   0.07f
#define BB    8
#define CC    128
#define HH    512
#define WW    512
#define HWSZ  (HH*WW)
#define KK    64
#define NNEG  7
#define PP    4096
#define NQ    (BB*KK)          // 512
#define CPAD  68               // pool smem row stride (words): 64 + 4 pad

// Device scratch (allocation-free)
__device__ float g_pool_n[PP * CC];     // normalized pool [P][C]
__device__ float g_q_norm[NQ * CC];     // normalized queries [NQ][C]
__device__ float g_pmax_val[NQ * 64];   // per (query, pool-block) max sim
__device__ int   g_pmax_idx[NQ * 64];
__device__ float g_loss[NQ];

// ---------------------------------------------------------------------------
// Kernel 1: prep — normalize pool (blocks 0..511, 8 rows each, warp per row)
//                  + gather/normalize queries (blocks 512..767, 2 per block)
// ---------------------------------------------------------------------------
__global__ void __launch_bounds__(256)
prep_kernel(const float* __restrict__ pool,
            const float* __restrict__ qf,
            const int*   __restrict__ qidx) {
    int t = threadIdx.x;
    if (blockIdx.x < 512) {
        // ---- pool rows: warp w handles row blockIdx.x*8 + w
        int w = t >> 5, lane = t & 31;
        int r = blockIdx.x * 8 + w;
        float4 v = ((const float4*)pool)[r * 32 + lane];
        float ss = v.x*v.x + v.y*v.y + v.z*v.z + v.w*v.w;
        #pragma unroll
        for (int o = 16; o > 0; o >>= 1) ss += __shfl_xor_sync(0xFFFFFFFFu, ss, o);
        float inv = 1.0f / fmaxf(sqrtf(ss), 1e-12f);
        v.x *= inv; v.y *= inv; v.z *= inv; v.w *= inv;
        ((float4*)g_pool_n)[r * 32 + lane] = v;
    } else {
        // ---- queries: 2 per block, 128 threads each (thread = channel)
        __shared__ float sred[2][4];
        __shared__ float sinv[2];
        int half = t >> 7;               // which query in this block
        int c = t & 127;
        int qb = (blockIdx.x - 512) * 2 + half;
        int b = qb >> 6, k = qb & 63;
        int idx = qidx[b * KK + k];
        float v = qf[(long)(b * CC + c) * HWSZ + idx];
        float ss = v * v;
        #pragma unroll
        for (int o = 16; o > 0; o >>= 1) ss += __shfl_xor_sync(0xFFFFFFFFu, ss, o);
        if ((t & 31) == 0) sred[half][(t >> 5) & 3] = ss;
        __syncthreads();
        if ((t & 127) == 0) {
            float s = sred[half][0] + sred[half][1] + sred[half][2] + sred[half][3];
            sinv[half] = 1.0f / fmaxf(sqrtf(s), 1e-12f);
        }
        __syncthreads();
        g_q_norm[qb * CC + c] = v * sinv[half];
    }
}

// ---------------------------------------------------------------------------
// Kernel 2: tiled GEMM + per-tile argmax.
// grid = (64 pool-blocks, 8 query-blocks), 256 threads.
// Block tile: 64 queries x 64 pool rows; thread micro-tile 4x4.
// tx = t&15 -> pool rows {tx, tx+16, tx+32, tx+48}; ty = t>>4 -> queries ty*4..+3.
// K split into two 64-channel chunks staged through smem.
// ---------------------------------------------------------------------------
__global__ void __launch_bounds__(256)
main_gemm_kernel() {
    __shared__ float q_s[64 * 64];     // [row][c], stride 64 (broadcast reads)
    __shared__ float p_s[64 * CPAD];   // [row][c], stride 68 (2-way max)

    int t = threadIdx.x;
    int tx = t & 15, ty = t >> 4;
    int pblk = blockIdx.x, qblk = blockIdx.y;
    int qbase = qblk * 64, pbase = pblk * 64;

    float acc[4][4];
    #pragma unroll
    for (int i = 0; i < 4; i++)
        #pragma unroll
        for (int j = 0; j < 4; j++) acc[i][j] = 0.0f;

    for (int kc = 0; kc < 2; kc++) {
        if (kc) __syncthreads();
        // load tiles: 1024 float4 each, 4 per thread, coalesced
        #pragma unroll
        for (int it = 0; it < 4; it++) {
            int idx = t + it * 256;
            int r = idx >> 4;          // 0..63
            int c4 = idx & 15;         // 0..15
            float4 v = ((const float4*)g_q_norm)[(qbase + r) * 32 + kc * 16 + c4];
            *(float4*)(q_s + r * 64 + c4 * 4) = v;
            float4 u = ((const float4*)g_pool_n)[(pbase + r) * 32 + kc * 16 + c4];
            *(float4*)(p_s + r * CPAD + c4 * 4) = u;
        }
        __syncthreads();

        #pragma unroll 4
        for (int c4 = 0; c4 < 16; c4++) {
            float4 qv[4], pv[4];
            #pragma unroll
            for (int qi = 0; qi < 4; qi++)
                qv[qi] = *(const float4*)(q_s + (ty * 4 + qi) * 64 + c4 * 4);
            #pragma unroll
            for (int pj = 0; pj < 4; pj++)
                pv[pj] = *(const float4*)(p_s + (tx + 16 * pj) * CPAD + c4 * 4);
            #pragma unroll
            for (int qi = 0; qi < 4; qi++)
                #pragma unroll
                for (int pj = 0; pj < 4; pj++)
                    acc[qi][pj] += qv[qi].x * pv[pj].x + qv[qi].y * pv[pj].y
                                 + qv[qi].z * pv[pj].z + qv[qi].w * pv[pj].w;
        }
    }

    // ---- per-thread argmax over its 4 pool rows, per query
    float bv[4]; int bi[4];
    #pragma unroll
    for (int qi = 0; qi < 4; qi++) {
        bv[qi] = acc[qi][0]; bi[qi] = pbase + tx;
        #pragma unroll
        for (int pj = 1; pj < 4; pj++) {
            int p = pbase + tx + 16 * pj;
            if (acc[qi][pj] > bv[qi]) { bv[qi] = acc[qi][pj]; bi[qi] = p; }
        }
    }
    // ---- reduce over tx (16 lanes; xor shuffles stay in 16-lane groups)
    #pragma unroll
    for (int o = 8; o > 0; o >>= 1) {
        #pragma unroll
        for (int qi = 0; qi < 4; qi++) {
            float ov = __shfl_xor_sync(0xFFFFFFFFu, bv[qi], o);
            int   oi = __shfl_xor_sync(0xFFFFFFFFu, bi[qi], o);
            if (ov > bv[qi] || (ov == bv[qi] && oi < bi[qi])) { bv[qi] = ov; bi[qi] = oi; }
        }
    }
    if (tx == 0) {
        #pragma unroll
        for (int qi = 0; qi < 4; qi++) {
            int q = qbase + ty * 4 + qi;
            g_pmax_val[q * 64 + pblk] = bv[qi];
            g_pmax_idx[q * 64 + pblk] = bi[qi];
        }
    }
}

// ---------------------------------------------------------------------------
// Kernel 3: finalize — warp per query: argmax over 64 partials, negatives,
// softmax-CE loss. grid = 64 blocks x 256 threads (512 warps).
// ---------------------------------------------------------------------------
__global__ void __launch_bounds__(256)
finalize_kernel(const float* __restrict__ negs) {
    int t = threadIdx.x, w = t >> 5, lane = t & 31;
    int q = blockIdx.x * 8 + w;
    int b = q >> 6, k = q & 63;

    // argmax over 64 (val, idx) partials: 2 per lane, then bfly reduce
    float v1 = g_pmax_val[q * 64 + lane];
    int   i1 = g_pmax_idx[q * 64 + lane];
    float v2 = g_pmax_val[q * 64 + 32 + lane];
    int   i2 = g_pmax_idx[q * 64 + 32 + lane];
    if (v2 > v1 || (v2 == v1 && i2 < i1)) { v1 = v2; i1 = i2; }
    #pragma unroll
    for (int o = 16; o > 0; o >>= 1) {
        float ov = __shfl_xor_sync(0xFFFFFFFFu, v1, o);
        int   oi = __shfl_xor_sync(0xFFFFFFFFu, i1, o);
        if (ov > v1 || (ov == v1 && oi < i1)) { v1 = ov; i1 = oi; }
    }
    // all lanes now hold (max sim) -> l[0]
    float l[1 + NNEG];
    l[0] = v1 / TAU;

    float4 qv = ((const float4*)(g_q_norm + q * CC))[lane];
    #pragma unroll
    for (int n = 0; n < NNEG; n++) {
        const float4* np = (const float4*)(negs + (((long)(b * KK + k)) * NNEG + n) * CC);
        float4 nv = np[lane];
        float ss = nv.x*nv.x + nv.y*nv.y + nv.z*nv.z + nv.w*nv.w;
        float dt = nv.x*qv.x + nv.y*qv.y + nv.z*qv.z + nv.w*qv.w;
        #pragma unroll
        for (int o = 16; o > 0; o >>= 1) {
            ss += __shfl_xor_sync(0xFFFFFFFFu, ss, o);
            dt += __shfl_xor_sync(0xFFFFFFFFu, dt, o);
        }
        l[n + 1] = (dt / fmaxf(sqrtf(ss), 1e-12f)) / TAU;
    }
    if (lane == 0) {
        float m = l[0];
        #pragma unroll
        for (int i = 1; i <= NNEG; i++) m = fmaxf(m, l[i]);
        float sum = 0.0f;
        #pragma unroll
        for (int i = 0; i <= NNEG; i++) sum += expf(l[i] - m);
        g_loss[q] = m + logf(sum) - l[0];
    }
}

// ---------------------------------------------------------------------------
// Kernel 4: deterministic mean over 512 per-query losses
// ---------------------------------------------------------------------------
__global__ void sum_kernel(float* __restrict__ out) {
    __shared__ float red[512];
    int t = threadIdx.x;
    red[t] = g_loss[t];
    __syncthreads();
    #pragma unroll
    for (int s = 256; s >= 1; s >>= 1) {
        if (t < s) red[t] += red[t + s];
        __syncthreads();
    }
    if (t == 0) out[0] = red[0] / (float)NQ;
}

extern "C" void kernel_launch(void* const* d_in, const int* in_sizes, int n_in,
                              void* d_out, int out_size) {
    const float* query_feat = (const float*)d_in[0];
    const float* pos_pool   = (const float*)d_in[1];
    const float* neg_protos = (const float*)d_in[2];
    const int*   query_idx  = (const int*)d_in[3];
    float* out = (float*)d_out;

    prep_kernel<<<768, 256>>>(pos_pool, query_feat, query_idx);
    dim3 grid(64, 8);
    main_gemm_kernel<<<grid, 256>>>();
    finalize_kernel<<<64, 256>>>(neg_protos);
    sum_kernel<<<1, 512>>>(out);
}